// round 14
// baseline (speedup 1.0000x reference)
#include <cuda_runtime.h>
#include <cstdint>
#include <cstddef>
#include <type_traits>

constexpr int Bn = 8, Tn = 4096, Mn = 1024;
constexpr int THREADS = 256;          // each thread owns one float2 lane
constexpr int M2 = Mn / 2;            // 512 float2 per timestep
constexpr int CHUNKS = M2 / THREADS;  // 2
constexpr int STRIP = 64;             // timesteps per block
constexpr int NSTRIPS = Tn / STRIP;   // 64
constexpr float EPSF = 1e-6f;

// Bump taps K[d] = exp(1 - 1/(1 - (d/15)^2 + 1e-6)), d=0..14 (K[15] == 0.0f in f32).
// Literals -> FFMA-imm form (rt_SMSP=1, zero tap registers).
__device__ constexpr float TAP[15] = {
    1.00000100f, 0.99554666f, 0.98206428f, 0.95919015f, 0.92630340f,
    0.88249802f, 0.82656660f, 0.75698827f, 0.67198882f, 0.56978420f,
    0.44933042f, 0.31240435f, 0.16901461f, 0.04890669f, 0.00116090f};

__device__ constexpr float PSUM[16] = {
    1.00000100f, 1.99554766f, 2.97761194f, 3.93680209f, 4.86310549f,
    5.74560351f, 6.57217011f, 7.32915838f, 8.00114720f, 8.57093140f,
    9.02026182f, 9.33266617f, 9.50168078f, 9.55058747f, 9.55174837f,
    9.55174837f};

// 3 CTAs/SM (24 warps): the straight-line 4-buffer rotation needs only ~80
// regs (measured in R6), which fits the 85-reg budget without spilling.
__global__ void __launch_bounds__(THREADS, 3)
bump_conv_kernel(const float2* __restrict__ x,
                 const float*  __restrict__ gate_raw,
                 float2*       __restrict__ out) {
    const int mp = blockIdx.x * THREADS + threadIdx.x;  // float2 lane in [0, 512)
    const int b  = blockIdx.z;
    const int t0 = blockIdx.y * STRIP;

    const float g0 = log1pf(__expf(gate_raw[2 * mp]));
    const float g1 = log1pf(__expf(gate_raw[2 * mp + 1]));
    const float rS = 1.0f / fmaxf(PSUM[15], EPSF);
    const float c0 = g0 * rS, c1 = g1 * rS;

    const size_t base = ((size_t)b * Tn + t0) * M2 + mp;
    const float2* xp = x + base;
    float2*       op = out + base;

    // 4 rotating 8-timestep buffers: cur, prev1, prev2 (15-tap window) + prefetch.
    float2 R0[8], R1[8], R2[8], R3[8];

    auto load8 = [&](float2 (&buf)[8], int tb) {
#pragma unroll
        for (int j = 0; j < 8; ++j) buf[j] = xp[(tb + j) * M2];  // imm offsets
    };

    // out[tb+j] = sum_{d=0..14} TAP[d] * x[tb+j-d]
    // cur = group tb, p1 = tb-8, p2 = tb-16 (only indices >= 2 of p2 read).
    // Streaming stores (.cs): out is write-once; keep x resident in L2.
    auto comp8 = [&](auto per_row, const float2 (&cur)[8], const float2 (&p1)[8],
                     const float2 (&p2)[8], int tb) {
#pragma unroll
        for (int j = 0; j < 8; ++j) {
            float ax = TAP[0] * cur[j].x;
            float ay = TAP[0] * cur[j].y;
#pragma unroll
            for (int d = 1; d < 15; ++d) {  // j, d compile-time -> static selection
                if (d <= j) {
                    ax = fmaf(TAP[d], cur[j - d].x, ax);
                    ay = fmaf(TAP[d], cur[j - d].y, ay);
                } else if (d <= j + 8) {
                    ax = fmaf(TAP[d], p1[j - d + 8].x, ax);
                    ay = fmaf(TAP[d], p1[j - d + 8].y, ay);
                } else {
                    ax = fmaf(TAP[d], p2[j - d + 16].x, ax);
                    ay = fmaf(TAP[d], p2[j - d + 16].y, ay);
                }
            }
            float s0, s1;
            if constexpr (decltype(per_row)::value) {
                float rj = 1.0f / fmaxf(PSUM[tb + j], EPSF);  // rows t = 0..15
                s0 = g0 * rj; s1 = g1 * rj;
            } else {
                s0 = c0; s1 = c1;
            }
            __stcs(&op[(tb + j) * M2], make_float2(ax * s0, ay * s1));
        }
    };

    constexpr std::false_type F{};

    // ---- prologue: history groups -2, -1 then groups 0, 1 ----
    if (t0 == 0) {
#pragma unroll
        for (int k = 0; k < 8; ++k) { R2[k] = make_float2(0.f, 0.f);
                                      R3[k] = make_float2(0.f, 0.f); }
        load8(R0, 0);
        load8(R1, 8);
        comp8(std::true_type{}, R0, R3, R2, 0);   // t = 0..7  per-row normalizer
        load8(R2, 16);                            // prefetch g=2
        comp8(std::true_type{}, R1, R0, R3, 8);   // t = 8..15 per-row normalizer
    } else {
        load8(R2, -16);   // halo group -2 (idx 0,1 unused but in-bounds: t0 >= 64)
        load8(R3, -8);    // halo group -1
        load8(R0, 0);
        load8(R1, 8);
        comp8(F, R0, R3, R2, 0);
        load8(R2, 16);                            // prefetch g=2
        comp8(F, R1, R0, R3, 8);
    }

    // ---- steady pipeline: load(g+1) issued before comp(g) ----
    load8(R3, 24);            // g=3
    comp8(F, R2, R1, R0, 16); // g=2
    load8(R0, 32);            // g=4
    comp8(F, R3, R2, R1, 24); // g=3
    load8(R1, 40);            // g=5
    comp8(F, R0, R3, R2, 32); // g=4
    load8(R2, 48);            // g=6
    comp8(F, R1, R0, R3, 40); // g=5
    load8(R3, 56);            // g=7
    comp8(F, R2, R1, R0, 48); // g=6
    comp8(F, R3, R2, R1, 56); // g=7
}

extern "C" void kernel_launch(void* const* d_in, const int* in_sizes, int n_in,
                              void* d_out, int out_size) {
    const float* x        = (const float*)d_in[0];
    // d_in[1] (mask) is exactly tril(ones); already encoded in the causal taps.
    const float* gate_raw = (const float*)d_in[2];

    dim3 grid(CHUNKS, NSTRIPS, Bn);
    bump_conv_kernel<<<grid, THREADS>>>((const float2*)x, gate_raw, (float2*)d_out);
}

// round 15
// speedup vs baseline: 1.4515x; 1.4515x over previous
#include <cuda_runtime.h>
#include <cstdint>
#include <cstddef>
#include <type_traits>

constexpr int Bn = 8, Tn = 4096, Mn = 1024;
constexpr int THREADS = 256;          // each thread owns one float2 lane
constexpr int M2 = Mn / 2;            // 512 float2 per timestep
constexpr int CHUNKS = M2 / THREADS;  // 2
constexpr int STRIP = 32;             // small tiles -> ~1% wave quantization
constexpr int NSTRIPS = Tn / STRIP;   // 128
constexpr float EPSF = 1e-6f;

// Bump taps K[d] = exp(1 - 1/(1 - (d/15)^2 + 1e-6)), d=0..14 (K[15] == 0.0f in f32).
// Literals -> FFMA-imm form (rt_SMSP=1, zero tap registers).
__device__ constexpr float TAP[15] = {
    1.00000100f, 0.99554666f, 0.98206428f, 0.95919015f, 0.92630340f,
    0.88249802f, 0.82656660f, 0.75698827f, 0.67198882f, 0.56978420f,
    0.44933042f, 0.31240435f, 0.16901461f, 0.04890669f, 0.00116090f};

__device__ constexpr float PSUM[16] = {
    1.00000100f, 1.99554766f, 2.97761194f, 3.93680209f, 4.86310549f,
    5.74560351f, 6.57217011f, 7.32915838f, 8.00114720f, 8.57093140f,
    9.02026182f, 9.33266617f, 9.50168078f, 9.55058747f, 9.55174837f,
    9.55174837f};

__global__ void __launch_bounds__(THREADS, 2)
bump_conv_kernel(const float2* __restrict__ x,
                 const float*  __restrict__ gate_raw,
                 float2*       __restrict__ out) {
    const int mp = blockIdx.x * THREADS + threadIdx.x;  // float2 lane in [0, 512)
    const int b  = blockIdx.z;
    const int t0 = blockIdx.y * STRIP;

    const float g0 = log1pf(__expf(gate_raw[2 * mp]));
    const float g1 = log1pf(__expf(gate_raw[2 * mp + 1]));
    const float rS = 1.0f / fmaxf(PSUM[15], EPSF);
    const float c0 = g0 * rS, c1 = g1 * rS;

    const size_t base = ((size_t)b * Tn + t0) * M2 + mp;
    const float2* xp = x + base;
    float2*       op = out + base;

    // 5 rotating 8-timestep buffers: cur, prev1, prev2 (15-tap window)
    // + two prefetch slots (dist-2 prefetch, as in the best R13 schedule).
    float2 B0[8], B1[8], B2[8], B3[8], B4[8];

    auto load8 = [&](float2 (&buf)[8], int tb) {
#pragma unroll
        for (int j = 0; j < 8; ++j) buf[j] = xp[(tb + j) * M2];  // imm offsets
    };

    // out[tb+j] = sum_{d=0..14} TAP[d] * x[tb+j-d]
    // cur = group tb, p1 = tb-8, p2 = tb-16 (only idx >= 2 of p2 read).
    // Streaming stores (.cs): out is write-once; keep x resident in L2.
    auto comp8 = [&](auto per_row, const float2 (&cur)[8], const float2 (&p1)[8],
                     const float2 (&p2)[8], int tb) {
#pragma unroll
        for (int j = 0; j < 8; ++j) {
            float ax = TAP[0] * cur[j].x;
            float ay = TAP[0] * cur[j].y;
#pragma unroll
            for (int d = 1; d < 15; ++d) {  // j, d compile-time -> static selection
                if (d <= j) {
                    ax = fmaf(TAP[d], cur[j - d].x, ax);
                    ay = fmaf(TAP[d], cur[j - d].y, ay);
                } else if (d <= j + 8) {
                    ax = fmaf(TAP[d], p1[j - d + 8].x, ax);
                    ay = fmaf(TAP[d], p1[j - d + 8].y, ay);
                } else {
                    ax = fmaf(TAP[d], p2[j - d + 16].x, ax);
                    ay = fmaf(TAP[d], p2[j - d + 16].y, ay);
                }
            }
            float s0, s1;
            if constexpr (decltype(per_row)::value) {
                float rj = 1.0f / fmaxf(PSUM[tb + j], EPSF);  // rows t = 0..15
                s0 = g0 * rj; s1 = g1 * rj;
            } else {
                s0 = c0; s1 = c1;
            }
            __stcs(&op[(tb + j) * M2], make_float2(ax * s0, ay * s1));
        }
    };

    constexpr std::false_type F{};

    // STRIP = 32 -> groups g0..g3. Prologue holds 5 load batches in flight.
    // groups: -2 -> B3, -1 -> B4, 0 -> B0, 1 -> B1, 2 -> B2; then B3 <- g3.
    if (t0 == 0) {
#pragma unroll
        for (int k = 0; k < 8; ++k) { B3[k] = make_float2(0.f, 0.f);
                                      B4[k] = make_float2(0.f, 0.f); }
        load8(B0, 0);
        load8(B1, 8);
        load8(B2, 16);
        comp8(std::true_type{}, B0, B4, B3, 0);   // t = 0..7  per-row normalizer
        load8(B3, 24);                            // g=3
        comp8(std::true_type{}, B1, B0, B4, 8);   // t = 8..15 per-row normalizer
    } else {
        load8(B3, -16);   // halo g=-2 (idx 0,1 unused; in-bounds since t0 >= 32)
        load8(B4, -8);    // halo g=-1
        load8(B0, 0);
        load8(B1, 8);
        load8(B2, 16);
        comp8(F, B0, B4, B3, 0);                  // g=0
        load8(B3, 24);                            // g=3
        comp8(F, B1, B0, B4, 8);                  // g=1
    }
    comp8(F, B2, B1, B0, 16);  // g=2
    comp8(F, B3, B2, B1, 24);  // g=3
}

extern "C" void kernel_launch(void* const* d_in, const int* in_sizes, int n_in,
                              void* d_out, int out_size) {
    const float* x        = (const float*)d_in[0];
    // d_in[1] (mask) is exactly tril(ones); already encoded in the causal taps.
    const float* gate_raw = (const float*)d_in[2];

    dim3 grid(CHUNKS, NSTRIPS, Bn);
    bump_conv_kernel<<<grid, THREADS>>>((const float2*)x, gate_raw, (float2*)d_out);
}